// round 9
// baseline (speedup 1.0000x reference)
#include <cuda_runtime.h>

#define BB 512      // batch rows = threads per block
#define NW 16       // warps per block
#define LL 100      // labels
#define DLEN 100000
#define GAMMA 0.9f

__device__ float g_per_label[LL];
__device__ unsigned int g_cnt = 0;

// Packed f32x2 mainloop over this thread's 1/K interleaved slice.
// Per 16B chunk: 2x add.rn.f32x2 + 4x max.f32 + 2x fma.rn.f32x2.
template<int K>
__device__ __forceinline__ void compute_sums_pk(
    const ulonglong2* __restrict__ fp2, const ulonglong2* __restrict__ fpp2,
    int np4, unsigned long long c2, int sub, float& S_all, float& S_pos)
{
    unsigned long long a0 = 0ull, a1 = 0ull;
#pragma unroll 8
    for (int jj = 0; jj < 128 / K; jj++) {
        ulonglong2 v = fp2[K * jj + sub];
        asm("{\n\t"
            ".reg .b64 e0, e1;\n\t"
            ".reg .f32 x0, x1, x2, x3;\n\t"
            "add.rn.f32x2 e0, %2, %4;\n\t"
            "add.rn.f32x2 e1, %3, %4;\n\t"
            "mov.b64 {x0, x1}, e0;\n\t"
            "mov.b64 {x2, x3}, e1;\n\t"
            "max.f32 x0, x0, 0f00000000;\n\t"
            "max.f32 x1, x1, 0f00000000;\n\t"
            "max.f32 x2, x2, 0f00000000;\n\t"
            "max.f32 x3, x3, 0f00000000;\n\t"
            "mov.b64 e0, {x0, x1};\n\t"
            "mov.b64 e1, {x2, x3};\n\t"
            "fma.rn.f32x2 %0, e0, e0, %0;\n\t"
            "fma.rn.f32x2 %1, e1, e1, %1;\n\t"
            "}" : "+l"(a0), "+l"(a1) : "l"(v.x), "l"(v.y), "l"(c2));
    }
    {
        float l0, h0, l1, h1;
        asm("mov.b64 {%0, %1}, %2;" : "=f"(l0), "=f"(h0) : "l"(a0));
        asm("mov.b64 {%0, %1}, %2;" : "=f"(l1), "=f"(h1) : "l"(a1));
        S_all = (l0 + h0) + (l1 + h1);
    }

    unsigned long long p0 = 0ull, p1 = 0ull;
    const int h = np4 / K;              // np4 is a multiple of 4
#pragma unroll 4
    for (int jj = 0; jj < h; jj++) {
        ulonglong2 v = fpp2[K * jj + sub];
        asm("{\n\t"
            ".reg .b64 e0, e1;\n\t"
            ".reg .f32 x0, x1, x2, x3;\n\t"
            "add.rn.f32x2 e0, %2, %4;\n\t"
            "add.rn.f32x2 e1, %3, %4;\n\t"
            "mov.b64 {x0, x1}, e0;\n\t"
            "mov.b64 {x2, x3}, e1;\n\t"
            "max.f32 x0, x0, 0f00000000;\n\t"
            "max.f32 x1, x1, 0f00000000;\n\t"
            "max.f32 x2, x2, 0f00000000;\n\t"
            "max.f32 x3, x3, 0f00000000;\n\t"
            "mov.b64 e0, {x0, x1};\n\t"
            "mov.b64 e1, {x2, x3};\n\t"
            "fma.rn.f32x2 %0, e0, e0, %0;\n\t"
            "fma.rn.f32x2 %1, e1, e1, %1;\n\t"
            "}" : "+l"(p0), "+l"(p1) : "l"(v.x), "l"(v.y), "l"(c2));
    }
    {
        float l0, h0, l1, h1;
        asm("mov.b64 {%0, %1}, %2;" : "=f"(l0), "=f"(h0) : "l"(p0));
        asm("mov.b64 {%0, %1}, %2;" : "=f"(l1), "=f"(h1) : "l"(p1));
        S_pos = (l0 + h0) + (l1 + h1);
    }
}

__global__ __launch_bounds__(BB, 1) void map_loss_fused_kernel(
    const float* __restrict__ y_pred,   // (B, L)
    const float* __restrict__ y_true,   // (B, L)
    const int*   __restrict__ index,    // (B,)
    const float* __restrict__ u_all,    // (L, DLEN)
    const float* __restrict__ u_pos,    // (L, DLEN)
    float* __restrict__ out)
{
    __shared__ __align__(16) float s_fp[BB];
    __shared__ __align__(16) float s_fpp[BB + 16];   // compacted positives (+pad)
    __shared__ float s_Sa[BB];          // per-slot S_all
    __shared__ float s_Sp[BB];          // per-slot S_pos
    __shared__ int   s_wcnt[NW];
    __shared__ float s_wsum[NW];
    __shared__ int   s_last;

    const int l    = blockIdx.x;
    const int t    = threadIdx.x;
    const int warp = t >> 5;
    const int lane = t & 31;

    // ---- issue all independent global loads immediately ----
    const int   idx  = index[t];
    const float fp_i = y_pred[t * LL + l];
    const float yt   = y_true[t * LL + l];
    const float ua_v = u_all[(long long)l * DLEN + idx];   // stay in regs
    const float up_v = u_pos[(long long)l * DLEN + idx];

    const bool pos_i = (yt == 1.0f);
    s_fp[t]  = fp_i;
    s_fpp[t] = -1e30f;                  // pad/clamped reads -> relu = 0
    if (t < 16) s_fpp[BB + t] = -1e30f;

    const unsigned m = __ballot_sync(0xffffffffu, pos_i);
    if (lane == 0) s_wcnt[warp] = __popc(m);
    __syncthreads();

    // ---- prefix over warp counts; deterministic compaction ----
    int base = 0, total = 0;
#pragma unroll
    for (int w = 0; w < NW; w++) {
        int cc = s_wcnt[w];
        if (w < warp) base += cc;
        total += cc;
    }
    int my_slot = -1;
    if (pos_i) {
        my_slot = base + __popc(m & ((1u << lane) - 1u));
        s_fpp[my_slot] = fp_i;
    }
    const int n_pos = total;                       // >= 1
    const int np4   = ((n_pos + 15) & ~15) >> 2;   // float4 count, multiple of 4
    __syncthreads();

    // ---- K selection (block-uniform) ----
    const int n4 = 4 * n_pos, n2 = 2 * n_pos;
    int n_act_thr, Ksel;
    if (n4 <= BB)      { Ksel = 4; n_act_thr = n4; }
    else if (n2 <= BB) { Ksel = 2; n_act_thr = n2; }
    else               { Ksel = 1; n_act_thr = n_pos; }
    const int n_act_wrp = (n_act_thr + 31) >> 5;

    if (warp < n_act_wrp) {             // warp-uniform; idle warps skip
        const bool act = t < n_act_thr;
        const ulonglong2* fp2  = reinterpret_cast<const ulonglong2*>(s_fp);
        const ulonglong2* fpp2 = reinterpret_cast<const ulonglong2*>(s_fpp);

        int slot, sub;
        float S_all = 0.f, S_pos = 0.f;
        if (Ksel == 4)      { slot = t >> 2; sub = t & 3; }
        else if (Ksel == 2) { slot = t >> 1; sub = t & 1; }
        else                { slot = t;      sub = 0;     }

        const float cs = act ? (1.0f - s_fpp[slot]) : -1e30f;
        unsigned long long c2;
        asm("mov.b64 %0, {%1, %1};" : "=l"(c2) : "f"(cs));

        if (Ksel == 4) {
            compute_sums_pk<4>(fp2, fpp2, np4, c2, sub, S_all, S_pos);
            S_all += __shfl_xor_sync(0xffffffffu, S_all, 1);
            S_all += __shfl_xor_sync(0xffffffffu, S_all, 2);
            S_pos += __shfl_xor_sync(0xffffffffu, S_pos, 1);
            S_pos += __shfl_xor_sync(0xffffffffu, S_pos, 2);
        } else if (Ksel == 2) {
            compute_sums_pk<2>(fp2, fpp2, np4, c2, sub, S_all, S_pos);
            S_all += __shfl_xor_sync(0xffffffffu, S_all, 1);
            S_pos += __shfl_xor_sync(0xffffffffu, S_pos, 1);
        } else {
            compute_sums_pk<1>(fp2, fpp2, np4, c2, sub, S_all, S_pos);
        }

        if (act && sub == 0) {          // publish per-slot sums
            s_Sa[slot] = S_all;
            s_Sp[slot] = S_pos;
        }
    }
    __syncthreads();

    // ---- each POSITIVE row thread computes its own contribution ----
    float contrib = 0.0f;
    if (pos_i) {
        const float Sa = s_Sa[my_slot];
        const float Sp = s_Sp[my_slot];
        const float ua_new = (1.0f - GAMMA) * ua_v + GAMMA * (Sa * (1.0f / (float)BB));
        const float up_new = (1.0f - GAMMA) * up_v + GAMMA * (Sp * (1.0f / (float)BB));
        contrib = (up_new * Sa - ua_new * Sp) / (ua_new * ua_new);
    }

    // ---- block reduction: warp shuffle + cross-warp fold (deterministic) ----
    float v = contrib;
#pragma unroll
    for (int off = 16; off > 0; off >>= 1)
        v += __shfl_down_sync(0xffffffffu, v, off);
    if (lane == 0) s_wsum[warp] = v;
    __syncthreads();

    if (warp == 0) {
        float v2 = (lane < NW) ? s_wsum[lane] : 0.0f;
#pragma unroll
        for (int off = 16; off > 0; off >>= 1)
            v2 += __shfl_down_sync(0xffffffffu, v2, off);
        if (lane == 0) {
            g_per_label[l] = v2 / ((float)n_pos * (float)BB);
            __threadfence();
            const unsigned old = atomicAdd(&g_cnt, 1u);
            s_last = (old == LL - 1) ? 1 : 0;
        }
    }
    __syncthreads();

    // ---- last block folds the 100 per-label values (fixed order) ----
    if (s_last && warp == 0) {
        __threadfence();
        volatile float* gp = g_per_label;
        float a = 0.0f;
#pragma unroll
        for (int j = 0; j < 4; j++) {
            const int i2 = lane + j * 32;
            if (i2 < LL) a += gp[i2];
        }
#pragma unroll
        for (int off = 16; off > 0; off >>= 1)
            a += __shfl_down_sync(0xffffffffu, a, off);
        if (lane == 0) {
            out[0] = a / (float)LL;
            g_cnt = 0;                  // reset for next graph replay
        }
    }
}

extern "C" void kernel_launch(void* const* d_in, const int* in_sizes, int n_in,
                              void* d_out, int out_size) {
    const float* y_pred = (const float*)d_in[0];
    const float* y_true = (const float*)d_in[1];
    const int*   index  = (const int*)d_in[2];
    const float* u_all  = (const float*)d_in[3];
    const float* u_pos  = (const float*)d_in[4];
    float* out = (float*)d_out;

    map_loss_fused_kernel<<<LL, BB>>>(y_pred, y_true, index, u_all, u_pos, out);
}

// round 10
// speedup vs baseline: 1.0268x; 1.0268x over previous
#include <cuda_runtime.h>

#define BB 512      // batch rows = threads per block
#define NW 16       // warps per block
#define LL 100      // labels
#define DLEN 100000
#define GAMMA 0.9f

__device__ float g_per_label[LL];
__device__ unsigned int g_cnt = 0;

// Packed f32x2 mainloop over this thread's 1/K interleaved slice.
template<int K>
__device__ __forceinline__ void compute_sums_pk(
    const ulonglong2* __restrict__ fp2, const ulonglong2* __restrict__ fpp2,
    int np4, unsigned long long c2, int sub, float& S_all, float& S_pos)
{
    unsigned long long a0 = 0ull, a1 = 0ull;
#pragma unroll 8
    for (int jj = 0; jj < 128 / K; jj++) {
        ulonglong2 v = fp2[K * jj + sub];
        asm("{\n\t"
            ".reg .b64 e0, e1;\n\t"
            ".reg .f32 x0, x1, x2, x3;\n\t"
            "add.rn.f32x2 e0, %2, %4;\n\t"
            "add.rn.f32x2 e1, %3, %4;\n\t"
            "mov.b64 {x0, x1}, e0;\n\t"
            "mov.b64 {x2, x3}, e1;\n\t"
            "max.f32 x0, x0, 0f00000000;\n\t"
            "max.f32 x1, x1, 0f00000000;\n\t"
            "max.f32 x2, x2, 0f00000000;\n\t"
            "max.f32 x3, x3, 0f00000000;\n\t"
            "mov.b64 e0, {x0, x1};\n\t"
            "mov.b64 e1, {x2, x3};\n\t"
            "fma.rn.f32x2 %0, e0, e0, %0;\n\t"
            "fma.rn.f32x2 %1, e1, e1, %1;\n\t"
            "}" : "+l"(a0), "+l"(a1) : "l"(v.x), "l"(v.y), "l"(c2));
    }
    {
        float l0, h0, l1, h1;
        asm("mov.b64 {%0, %1}, %2;" : "=f"(l0), "=f"(h0) : "l"(a0));
        asm("mov.b64 {%0, %1}, %2;" : "=f"(l1), "=f"(h1) : "l"(a1));
        S_all = (l0 + h0) + (l1 + h1);
    }

    unsigned long long p0 = 0ull, p1 = 0ull;
    const int h = np4 / K;              // np4 is a multiple of 4
#pragma unroll 4
    for (int jj = 0; jj < h; jj++) {
        ulonglong2 v = fpp2[K * jj + sub];
        asm("{\n\t"
            ".reg .b64 e0, e1;\n\t"
            ".reg .f32 x0, x1, x2, x3;\n\t"
            "add.rn.f32x2 e0, %2, %4;\n\t"
            "add.rn.f32x2 e1, %3, %4;\n\t"
            "mov.b64 {x0, x1}, e0;\n\t"
            "mov.b64 {x2, x3}, e1;\n\t"
            "max.f32 x0, x0, 0f00000000;\n\t"
            "max.f32 x1, x1, 0f00000000;\n\t"
            "max.f32 x2, x2, 0f00000000;\n\t"
            "max.f32 x3, x3, 0f00000000;\n\t"
            "mov.b64 e0, {x0, x1};\n\t"
            "mov.b64 e1, {x2, x3};\n\t"
            "fma.rn.f32x2 %0, e0, e0, %0;\n\t"
            "fma.rn.f32x2 %1, e1, e1, %1;\n\t"
            "}" : "+l"(p0), "+l"(p1) : "l"(v.x), "l"(v.y), "l"(c2));
    }
    {
        float l0, h0, l1, h1;
        asm("mov.b64 {%0, %1}, %2;" : "=f"(l0), "=f"(h0) : "l"(p0));
        asm("mov.b64 {%0, %1}, %2;" : "=f"(l1), "=f"(h1) : "l"(p1));
        S_pos = (l0 + h0) + (l1 + h1);
    }
}

__global__ __launch_bounds__(BB, 1) void map_loss_fused_kernel(
    const float* __restrict__ y_pred,   // (B, L)
    const float* __restrict__ y_true,   // (B, L)
    const int*   __restrict__ index,    // (B,)
    const float* __restrict__ u_all,    // (L, DLEN)
    const float* __restrict__ u_pos,    // (L, DLEN)
    float* __restrict__ out)
{
    __shared__ __align__(16) float s_fp[BB];
    __shared__ __align__(16) float s_fpp[BB + 16];   // compacted positives (+pad)
    __shared__ int   s_prow[BB];        // slot -> original row
    __shared__ int   s_wcnt[NW];
    __shared__ float s_wsum[NW];

    const int l    = blockIdx.x;
    const int t    = threadIdx.x;
    const int warp = t >> 5;
    const int lane = t & 31;

    // ---- front loads: only y_pred / y_true (u gathers come later, by slot) ----
    const float fp_i = y_pred[t * LL + l];
    const float yt   = y_true[t * LL + l];

    const bool pos_i = (yt == 1.0f);
    s_fp[t]  = fp_i;
    s_fpp[t] = -1e30f;                  // pad/clamped reads -> relu = 0
    if (t < 16) s_fpp[BB + t] = -1e30f;

    const unsigned m = __ballot_sync(0xffffffffu, pos_i);
    if (lane == 0) s_wcnt[warp] = __popc(m);
    __syncthreads();                                            // bar1

    // ---- prefix over warp counts; deterministic compaction ----
    int base = 0, total = 0;
#pragma unroll
    for (int w = 0; w < NW; w++) {
        int cc = s_wcnt[w];
        if (w < warp) base += cc;
        total += cc;
    }
    if (pos_i) {
        const int off = base + __popc(m & ((1u << lane) - 1u));
        s_fpp[off]  = fp_i;
        s_prow[off] = t;
    }
    const int n_pos = total;                       // >= 1
    const int np4   = ((n_pos + 15) & ~15) >> 2;   // float4 count, multiple of 4
    __syncthreads();                                            // bar2

    // ---- K selection (block-uniform) ----
    const int n4 = 4 * n_pos, n2 = 2 * n_pos;
    int n_act_thr, Ksel;
    if (n4 <= BB)      { Ksel = 4; n_act_thr = n4; }
    else if (n2 <= BB) { Ksel = 2; n_act_thr = n2; }
    else               { Ksel = 1; n_act_thr = n_pos; }
    const int n_act_wrp = (n_act_thr + 31) >> 5;

    float contrib = 0.0f;

    if (warp < n_act_wrp) {             // warp-uniform; idle warps skip
        const bool act = t < n_act_thr;
        int slot, sub;
        if (Ksel == 4)      { slot = t >> 2; sub = t & 3; }
        else if (Ksel == 2) { slot = t >> 1; sub = t & 1; }
        else                { slot = t;      sub = 0;     }

        // Slot-leader threads issue the u gathers NOW; their ~600-850cyc
        // latency overlaps the mainloop below. Only ~n_pos gathers total.
        float ua_v = 1.0f, up_v = 1.0f;
        if (act && sub == 0) {
            const int row = s_prow[slot];
            const int idx = index[row];
            ua_v = u_all[(long long)l * DLEN + idx];
            up_v = u_pos[(long long)l * DLEN + idx];
        }

        const float cs = act ? (1.0f - s_fpp[slot]) : -1e30f;
        unsigned long long c2;
        asm("mov.b64 %0, {%1, %1};" : "=l"(c2) : "f"(cs));

        const ulonglong2* fp2  = reinterpret_cast<const ulonglong2*>(s_fp);
        const ulonglong2* fpp2 = reinterpret_cast<const ulonglong2*>(s_fpp);

        float S_all = 0.f, S_pos = 0.f;
        if (Ksel == 4) {
            compute_sums_pk<4>(fp2, fpp2, np4, c2, sub, S_all, S_pos);
            S_all += __shfl_xor_sync(0xffffffffu, S_all, 1);
            S_all += __shfl_xor_sync(0xffffffffu, S_all, 2);
            S_pos += __shfl_xor_sync(0xffffffffu, S_pos, 1);
            S_pos += __shfl_xor_sync(0xffffffffu, S_pos, 2);
        } else if (Ksel == 2) {
            compute_sums_pk<2>(fp2, fpp2, np4, c2, sub, S_all, S_pos);
            S_all += __shfl_xor_sync(0xffffffffu, S_all, 1);
            S_pos += __shfl_xor_sync(0xffffffffu, S_pos, 1);
        } else {
            compute_sums_pk<1>(fp2, fpp2, np4, c2, sub, S_all, S_pos);
        }

        // Contribution computed directly on the slot leader (u arrived by now).
        if (act && sub == 0) {
            const float ua_new = (1.0f - GAMMA) * ua_v + GAMMA * (S_all * (1.0f / (float)BB));
            const float up_new = (1.0f - GAMMA) * up_v + GAMMA * (S_pos * (1.0f / (float)BB));
            contrib = (up_new * S_all - ua_new * S_pos) / (ua_new * ua_new);
        }
    }

    // ---- block reduction: warp shuffle + cross-warp fold (deterministic) ----
    float v = contrib;
#pragma unroll
    for (int off = 16; off > 0; off >>= 1)
        v += __shfl_down_sync(0xffffffffu, v, off);
    if (lane == 0) s_wsum[warp] = v;
    __syncthreads();                                            // bar3 (last)

    if (warp == 0) {
        float v2 = (lane < NW) ? s_wsum[lane] : 0.0f;
#pragma unroll
        for (int off = 16; off > 0; off >>= 1)
            v2 += __shfl_down_sync(0xffffffffu, v2, off);

        unsigned old = 0;
        if (lane == 0) {
            g_per_label[l] = v2 / ((float)n_pos * (float)BB);
            __threadfence();
            old = atomicAdd(&g_cnt, 1u);
        }
        old = __shfl_sync(0xffffffffu, old, 0);    // warp broadcast, no block bar

        if (old == LL - 1) {                        // last block: fold 100 values
            __threadfence();
            volatile float* gp = g_per_label;
            float a = 0.0f;
#pragma unroll
            for (int j = 0; j < 4; j++) {
                const int i2 = lane + j * 32;
                if (i2 < LL) a += gp[i2];
            }
#pragma unroll
            for (int off = 16; off > 0; off >>= 1)
                a += __shfl_down_sync(0xffffffffu, a, off);
            if (lane == 0) {
                out[0] = a / (float)LL;
                g_cnt = 0;                          // reset for next replay
            }
        }
    }
}

extern "C" void kernel_launch(void* const* d_in, const int* in_sizes, int n_in,
                              void* d_out, int out_size) {
    const float* y_pred = (const float*)d_in[0];
    const float* y_true = (const float*)d_in[1];
    const int*   index  = (const int*)d_in[2];
    const float* u_all  = (const float*)d_in[3];
    const float* u_pos  = (const float*)d_in[4];
    float* out = (float*)d_out;

    map_loss_fused_kernel<<<LL, BB>>>(y_pred, y_true, index, u_all, u_pos, out);
}

// round 11
// speedup vs baseline: 1.0299x; 1.0030x over previous
#include <cuda_runtime.h>

#define BB 512      // batch rows = threads per block
#define NW 16       // warps per block
#define LL 100      // labels
#define DLEN 100000
#define GAMMA 0.9f

__device__ float g_per_label[LL];
__device__ unsigned int g_cnt = 0;

// Packed f32x2 mainloop over this thread's 1/K interleaved slice.
template<int K>
__device__ __forceinline__ void compute_sums_pk(
    const ulonglong2* __restrict__ fp2, const ulonglong2* __restrict__ fpp2,
    int np4, unsigned long long c2, int sub, float& S_all, float& S_pos)
{
    unsigned long long a0 = 0ull, a1 = 0ull;
#pragma unroll 8
    for (int jj = 0; jj < 128 / K; jj++) {
        ulonglong2 v = fp2[K * jj + sub];
        asm("{\n\t"
            ".reg .b64 e0, e1;\n\t"
            ".reg .f32 x0, x1, x2, x3;\n\t"
            "add.rn.f32x2 e0, %2, %4;\n\t"
            "add.rn.f32x2 e1, %3, %4;\n\t"
            "mov.b64 {x0, x1}, e0;\n\t"
            "mov.b64 {x2, x3}, e1;\n\t"
            "max.f32 x0, x0, 0f00000000;\n\t"
            "max.f32 x1, x1, 0f00000000;\n\t"
            "max.f32 x2, x2, 0f00000000;\n\t"
            "max.f32 x3, x3, 0f00000000;\n\t"
            "mov.b64 e0, {x0, x1};\n\t"
            "mov.b64 e1, {x2, x3};\n\t"
            "fma.rn.f32x2 %0, e0, e0, %0;\n\t"
            "fma.rn.f32x2 %1, e1, e1, %1;\n\t"
            "}" : "+l"(a0), "+l"(a1) : "l"(v.x), "l"(v.y), "l"(c2));
    }
    {
        float l0, h0, l1, h1;
        asm("mov.b64 {%0, %1}, %2;" : "=f"(l0), "=f"(h0) : "l"(a0));
        asm("mov.b64 {%0, %1}, %2;" : "=f"(l1), "=f"(h1) : "l"(a1));
        S_all = (l0 + h0) + (l1 + h1);
    }

    unsigned long long p0 = 0ull, p1 = 0ull;
    const int h = np4 / K;              // np4 is a multiple of 4
#pragma unroll 4
    for (int jj = 0; jj < h; jj++) {
        ulonglong2 v = fpp2[K * jj + sub];
        asm("{\n\t"
            ".reg .b64 e0, e1;\n\t"
            ".reg .f32 x0, x1, x2, x3;\n\t"
            "add.rn.f32x2 e0, %2, %4;\n\t"
            "add.rn.f32x2 e1, %3, %4;\n\t"
            "mov.b64 {x0, x1}, e0;\n\t"
            "mov.b64 {x2, x3}, e1;\n\t"
            "max.f32 x0, x0, 0f00000000;\n\t"
            "max.f32 x1, x1, 0f00000000;\n\t"
            "max.f32 x2, x2, 0f00000000;\n\t"
            "max.f32 x3, x3, 0f00000000;\n\t"
            "mov.b64 e0, {x0, x1};\n\t"
            "mov.b64 e1, {x2, x3};\n\t"
            "fma.rn.f32x2 %0, e0, e0, %0;\n\t"
            "fma.rn.f32x2 %1, e1, e1, %1;\n\t"
            "}" : "+l"(p0), "+l"(p1) : "l"(v.x), "l"(v.y), "l"(c2));
    }
    {
        float l0, h0, l1, h1;
        asm("mov.b64 {%0, %1}, %2;" : "=f"(l0), "=f"(h0) : "l"(p0));
        asm("mov.b64 {%0, %1}, %2;" : "=f"(l1), "=f"(h1) : "l"(p1));
        S_pos = (l0 + h0) + (l1 + h1);
    }
}

__global__ __launch_bounds__(BB, 1) void map_loss_fused_kernel(
    const float* __restrict__ y_pred,   // (B, L)
    const float* __restrict__ y_true,   // (B, L)
    const int*   __restrict__ index,    // (B,)
    const float* __restrict__ u_all,    // (L, DLEN)
    const float* __restrict__ u_pos,    // (L, DLEN)
    float* __restrict__ out)
{
    __shared__ __align__(16) float s_fp[BB];
    __shared__ __align__(16) float s_fpp[BB + 16];   // compacted positives (+pad)
    __shared__ float s_Sa[BB];          // per-slot S_all
    __shared__ float s_Sp[BB];          // per-slot S_pos
    __shared__ int   s_wcnt[NW];
    __shared__ float s_wsum[NW];

    const int l    = blockIdx.x;
    const int t    = threadIdx.x;
    const int warp = t >> 5;
    const int lane = t & 31;

    // ---- issue ALL independent global loads immediately (R9 config: these
    // 512-wide u gathers are fully hidden under compaction + mainloop) ----
    const int   idx  = index[t];
    const float fp_i = y_pred[t * LL + l];
    const float yt   = y_true[t * LL + l];
    const float ua_v = u_all[(long long)l * DLEN + idx];   // stay in regs
    const float up_v = u_pos[(long long)l * DLEN + idx];

    const bool pos_i = (yt == 1.0f);
    s_fp[t]  = fp_i;
    s_fpp[t] = -1e30f;                  // pad/clamped reads -> relu = 0
    if (t < 16) s_fpp[BB + t] = -1e30f;

    const unsigned m = __ballot_sync(0xffffffffu, pos_i);
    if (lane == 0) s_wcnt[warp] = __popc(m);
    __syncthreads();                                            // bar1

    // ---- prefix over warp counts; deterministic compaction ----
    int base = 0, total = 0;
#pragma unroll
    for (int w = 0; w < NW; w++) {
        int cc = s_wcnt[w];
        if (w < warp) base += cc;
        total += cc;
    }
    int my_slot = -1;
    if (pos_i) {
        my_slot = base + __popc(m & ((1u << lane) - 1u));
        s_fpp[my_slot] = fp_i;
    }
    const int n_pos = total;                       // >= 1
    const int np4   = ((n_pos + 15) & ~15) >> 2;   // float4 count, multiple of 4
    __syncthreads();                                            // bar2

    // ---- K selection (block-uniform) ----
    const int n4 = 4 * n_pos, n2 = 2 * n_pos;
    int n_act_thr, Ksel;
    if (n4 <= BB)      { Ksel = 4; n_act_thr = n4; }
    else if (n2 <= BB) { Ksel = 2; n_act_thr = n2; }
    else               { Ksel = 1; n_act_thr = n_pos; }
    const int n_act_wrp = (n_act_thr + 31) >> 5;

    if (warp < n_act_wrp) {             // warp-uniform; idle warps skip
        const bool act = t < n_act_thr;
        const ulonglong2* fp2  = reinterpret_cast<const ulonglong2*>(s_fp);
        const ulonglong2* fpp2 = reinterpret_cast<const ulonglong2*>(s_fpp);

        int slot, sub;
        float S_all = 0.f, S_pos = 0.f;
        if (Ksel == 4)      { slot = t >> 2; sub = t & 3; }
        else if (Ksel == 2) { slot = t >> 1; sub = t & 1; }
        else                { slot = t;      sub = 0;     }

        const float cs = act ? (1.0f - s_fpp[slot]) : -1e30f;
        unsigned long long c2;
        asm("mov.b64 %0, {%1, %1};" : "=l"(c2) : "f"(cs));

        if (Ksel == 4) {
            compute_sums_pk<4>(fp2, fpp2, np4, c2, sub, S_all, S_pos);
            S_all += __shfl_xor_sync(0xffffffffu, S_all, 1);
            S_all += __shfl_xor_sync(0xffffffffu, S_all, 2);
            S_pos += __shfl_xor_sync(0xffffffffu, S_pos, 1);
            S_pos += __shfl_xor_sync(0xffffffffu, S_pos, 2);
        } else if (Ksel == 2) {
            compute_sums_pk<2>(fp2, fpp2, np4, c2, sub, S_all, S_pos);
            S_all += __shfl_xor_sync(0xffffffffu, S_all, 1);
            S_pos += __shfl_xor_sync(0xffffffffu, S_pos, 1);
        } else {
            compute_sums_pk<1>(fp2, fpp2, np4, c2, sub, S_all, S_pos);
        }

        if (act && sub == 0) {          // publish per-slot sums
            s_Sa[slot] = S_all;
            s_Sp[slot] = S_pos;
        }
    }
    __syncthreads();                                            // bar3

    // ---- each POSITIVE row thread computes its own contribution ----
    float contrib = 0.0f;
    if (pos_i) {
        const float Sa = s_Sa[my_slot];
        const float Sp = s_Sp[my_slot];
        const float ua_new = (1.0f - GAMMA) * ua_v + GAMMA * (Sa * (1.0f / (float)BB));
        const float up_new = (1.0f - GAMMA) * up_v + GAMMA * (Sp * (1.0f / (float)BB));
        contrib = (up_new * Sa - ua_new * Sp) / (ua_new * ua_new);
    }

    // ---- block reduction: warp shuffle + cross-warp fold (deterministic) ----
    float v = contrib;
#pragma unroll
    for (int off = 16; off > 0; off >>= 1)
        v += __shfl_down_sync(0xffffffffu, v, off);
    if (lane == 0) s_wsum[warp] = v;
    __syncthreads();                                            // bar4 (last)

    if (warp == 0) {
        float v2 = (lane < NW) ? s_wsum[lane] : 0.0f;
#pragma unroll
        for (int off = 16; off > 0; off >>= 1)
            v2 += __shfl_down_sync(0xffffffffu, v2, off);

        unsigned old = 0;
        if (lane == 0) {
            g_per_label[l] = v2 / ((float)n_pos * (float)BB);
            // acq_rel RMW: release orders the g_per_label store above;
            // acquire orders the last block's fold loads below.
            // Replaces two __threadfence() (MEMBAR.GPU) on the tail.
            unsigned* cnt_ptr = &g_cnt;
            asm volatile("atom.acq_rel.gpu.global.add.u32 %0, [%1], %2;"
                         : "=r"(old) : "l"(cnt_ptr), "r"(1u) : "memory");
        }
        old = __shfl_sync(0xffffffffu, old, 0);    // warp broadcast, no block bar

        if (old == LL - 1) {                        // last block: fold 100 values
            volatile float* gp = g_per_label;
            float a = 0.0f;
#pragma unroll
            for (int j = 0; j < 4; j++) {
                const int i2 = lane + j * 32;
                if (i2 < LL) a += gp[i2];
            }
#pragma unroll
            for (int off = 16; off > 0; off >>= 1)
                a += __shfl_down_sync(0xffffffffu, a, off);
            if (lane == 0) {
                out[0] = a / (float)LL;
                g_cnt = 0;                          // reset for next replay
            }
        }
    }
}

extern "C" void kernel_launch(void* const* d_in, const int* in_sizes, int n_in,
                              void* d_out, int out_size) {
    const float* y_pred = (const float*)d_in[0];
    const float* y_true = (const float*)d_in[1];
    const int*   index  = (const int*)d_in[2];
    const float* u_all  = (const float*)d_in[3];
    const float* u_pos  = (const float*)d_in[4];
    float* out = (float*)d_out;

    map_loss_fused_kernel<<<LL, BB>>>(y_pred, y_true, index, u_all, u_pos, out);
}

// round 12
// speedup vs baseline: 1.2684x; 1.2316x over previous
#include <cuda_runtime.h>

#define BB 512      // batch rows = threads per block
#define NW 16       // warps per block
#define LL 100      // labels
#define DLEN 100000
#define GAMMA 0.9f

__device__ float g_per_label[LL];
__device__ unsigned int g_cnt = 0;

// Packed f32x2 sweep over the SORTED array: positive prefix [0, np4) feeds
// S_pos; negative suffix [np4, np4+na4) feeds the remainder of S_all.
// Each thread takes the 1/K interleaved slice of both ranges.
template<int K>
__device__ __forceinline__ void compute_sums_sorted(
    const ulonglong2* __restrict__ srt2, int np4, int na4,
    unsigned long long c2, int sub, float& S_all, float& S_pos)
{
    // positive prefix
    unsigned long long p0 = 0ull, p1 = 0ull;
    const int hp = np4 / K;             // np4 multiple of 4 >= K
#pragma unroll 4
    for (int jj = 0; jj < hp; jj++) {
        ulonglong2 v = srt2[K * jj + sub];
        asm("{\n\t"
            ".reg .b64 e0, e1;\n\t"
            ".reg .f32 x0, x1, x2, x3;\n\t"
            "add.rn.f32x2 e0, %2, %4;\n\t"
            "add.rn.f32x2 e1, %3, %4;\n\t"
            "mov.b64 {x0, x1}, e0;\n\t"
            "mov.b64 {x2, x3}, e1;\n\t"
            "max.f32 x0, x0, 0f00000000;\n\t"
            "max.f32 x1, x1, 0f00000000;\n\t"
            "max.f32 x2, x2, 0f00000000;\n\t"
            "max.f32 x3, x3, 0f00000000;\n\t"
            "mov.b64 e0, {x0, x1};\n\t"
            "mov.b64 e1, {x2, x3};\n\t"
            "fma.rn.f32x2 %0, e0, e0, %0;\n\t"
            "fma.rn.f32x2 %1, e1, e1, %1;\n\t"
            "}" : "+l"(p0), "+l"(p1) : "l"(v.x), "l"(v.y), "l"(c2));
    }
    float pl0, ph0, pl1, ph1;
    asm("mov.b64 {%0, %1}, %2;" : "=f"(pl0), "=f"(ph0) : "l"(p0));
    asm("mov.b64 {%0, %1}, %2;" : "=f"(pl1), "=f"(ph1) : "l"(p1));
    S_pos = (pl0 + ph0) + (pl1 + ph1);

    // negative suffix
    unsigned long long a0 = 0ull, a1 = 0ull;
    const int ha = na4 / K;             // na4 multiple of 4
#pragma unroll 8
    for (int jj = 0; jj < ha; jj++) {
        ulonglong2 v = srt2[np4 + K * jj + sub];
        asm("{\n\t"
            ".reg .b64 e0, e1;\n\t"
            ".reg .f32 x0, x1, x2, x3;\n\t"
            "add.rn.f32x2 e0, %2, %4;\n\t"
            "add.rn.f32x2 e1, %3, %4;\n\t"
            "mov.b64 {x0, x1}, e0;\n\t"
            "mov.b64 {x2, x3}, e1;\n\t"
            "max.f32 x0, x0, 0f00000000;\n\t"
            "max.f32 x1, x1, 0f00000000;\n\t"
            "max.f32 x2, x2, 0f00000000;\n\t"
            "max.f32 x3, x3, 0f00000000;\n\t"
            "mov.b64 e0, {x0, x1};\n\t"
            "mov.b64 e1, {x2, x3};\n\t"
            "fma.rn.f32x2 %0, e0, e0, %0;\n\t"
            "fma.rn.f32x2 %1, e1, e1, %1;\n\t"
            "}" : "+l"(a0), "+l"(a1) : "l"(v.x), "l"(v.y), "l"(c2));
    }
    float al0, ah0, al1, ah1;
    asm("mov.b64 {%0, %1}, %2;" : "=f"(al0), "=f"(ah0) : "l"(a0));
    asm("mov.b64 {%0, %1}, %2;" : "=f"(al1), "=f"(ah1) : "l"(a1));
    S_all = S_pos + ((al0 + ah0) + (al1 + ah1));
}

__global__ __launch_bounds__(BB, 1) void map_loss_fused_kernel(
    const float* __restrict__ y_pred,   // (B, L)
    const float* __restrict__ y_true,   // (B, L)
    const int*   __restrict__ index,    // (B,)
    const float* __restrict__ u_all,    // (L, DLEN)
    const float* __restrict__ u_pos,    // (L, DLEN)
    float* __restrict__ out)
{
    // sorted fp: [0,n_pos) positives, pad to 16; then negatives, pad to 16.
    __shared__ __align__(16) float s_srt[BB + 32];
    __shared__ float s_Sa[BB];          // per-slot S_all
    __shared__ float s_Sp[BB];          // per-slot S_pos
    __shared__ int   s_wcnt[NW];
    __shared__ float s_wsum[NW];

    const int l    = blockIdx.x;
    const int t    = threadIdx.x;
    const int warp = t >> 5;
    const int lane = t & 31;

    // ---- issue ALL independent global loads immediately (hidden under
    // compaction + mainloop; R9/R11-verified best front config) ----
    const int   idx  = index[t];
    const float fp_i = y_pred[t * LL + l];
    const float yt   = y_true[t * LL + l];
    const float ua_v = u_all[(long long)l * DLEN + idx];   // stay in regs
    const float up_v = u_pos[(long long)l * DLEN + idx];

    const bool pos_i = (yt == 1.0f);
    s_srt[t] = -1e30f;                  // pad entries -> relu = 0
    if (t < 32) s_srt[BB + t] = -1e30f;

    const unsigned m = __ballot_sync(0xffffffffu, pos_i);
    if (lane == 0) s_wcnt[warp] = __popc(m);
    __syncthreads();                                            // bar1

    // ---- prefix over warp counts; deterministic 2-way compaction ----
    int base = 0, total = 0;
#pragma unroll
    for (int w = 0; w < NW; w++) {
        int cc = s_wcnt[w];
        if (w < warp) base += cc;
        total += cc;
    }
    const int n_pos      = total;                    // >= 1
    const int n_pos_pad  = (n_pos + 15) & ~15;
    const int np4        = n_pos_pad >> 2;           // multiple of 4
    const int n_neg      = BB - n_pos;
    const int na4        = ((n_neg + 15) & ~15) >> 2;

    const int lane_pos = __popc(m & ((1u << lane) - 1u));
    int my_slot = -1;
    if (pos_i) {
        my_slot = base + lane_pos;
        s_srt[my_slot] = fp_i;
    } else {
        // negative slot: negatives-before-me = (32*warp - base) + (lane - lane_pos)
        const int noff = (32 * warp - base) + (lane - lane_pos);
        s_srt[n_pos_pad + noff] = fp_i;
    }
    __syncthreads();                                            // bar2

    // ---- K selection (block-uniform) ----
    const int n4 = 4 * n_pos, n2 = 2 * n_pos;
    int n_act_thr, Ksel;
    if (n4 <= BB)      { Ksel = 4; n_act_thr = n4; }
    else if (n2 <= BB) { Ksel = 2; n_act_thr = n2; }
    else               { Ksel = 1; n_act_thr = n_pos; }
    const int n_act_wrp = (n_act_thr + 31) >> 5;

    if (warp < n_act_wrp) {             // warp-uniform; idle warps skip
        const bool act = t < n_act_thr;
        const ulonglong2* srt2 = reinterpret_cast<const ulonglong2*>(s_srt);

        int slot, sub;
        float S_all = 0.f, S_pos = 0.f;
        if (Ksel == 4)      { slot = t >> 2; sub = t & 3; }
        else if (Ksel == 2) { slot = t >> 1; sub = t & 1; }
        else                { slot = t;      sub = 0;     }

        const float cs = act ? (1.0f - s_srt[slot]) : -1e30f;
        unsigned long long c2;
        asm("mov.b64 %0, {%1, %1};" : "=l"(c2) : "f"(cs));

        if (Ksel == 4) {
            compute_sums_sorted<4>(srt2, np4, na4, c2, sub, S_all, S_pos);
            S_all += __shfl_xor_sync(0xffffffffu, S_all, 1);
            S_all += __shfl_xor_sync(0xffffffffu, S_all, 2);
            S_pos += __shfl_xor_sync(0xffffffffu, S_pos, 1);
            S_pos += __shfl_xor_sync(0xffffffffu, S_pos, 2);
        } else if (Ksel == 2) {
            compute_sums_sorted<2>(srt2, np4, na4, c2, sub, S_all, S_pos);
            S_all += __shfl_xor_sync(0xffffffffu, S_all, 1);
            S_pos += __shfl_xor_sync(0xffffffffu, S_pos, 1);
        } else {
            compute_sums_sorted<1>(srt2, np4, na4, c2, sub, S_all, S_pos);
        }

        if (act && sub == 0) {          // publish per-slot sums
            s_Sa[slot] = S_all;
            s_Sp[slot] = S_pos;
        }
    }
    __syncthreads();                                            // bar3

    // ---- each POSITIVE row thread computes its own contribution ----
    float contrib = 0.0f;
    if (pos_i) {
        const float Sa = s_Sa[my_slot];
        const float Sp = s_Sp[my_slot];
        const float ua_new = (1.0f - GAMMA) * ua_v + GAMMA * (Sa * (1.0f / (float)BB));
        const float up_new = (1.0f - GAMMA) * up_v + GAMMA * (Sp * (1.0f / (float)BB));
        contrib = (up_new * Sa - ua_new * Sp) / (ua_new * ua_new);
    }

    // ---- block reduction: warp shuffle + cross-warp fold (deterministic) ----
    float v = contrib;
#pragma unroll
    for (int off = 16; off > 0; off >>= 1)
        v += __shfl_down_sync(0xffffffffu, v, off);
    if (lane == 0) s_wsum[warp] = v;
    __syncthreads();                                            // bar4 (last)

    if (warp == 0) {
        float v2 = (lane < NW) ? s_wsum[lane] : 0.0f;
#pragma unroll
        for (int off = 16; off > 0; off >>= 1)
            v2 += __shfl_down_sync(0xffffffffu, v2, off);

        unsigned old = 0;
        if (lane == 0) {
            g_per_label[l] = v2 / ((float)n_pos * (float)BB);
            // acq_rel RMW: release orders the store above; acquire orders
            // the last block's fold loads. No MEMBAR.GPU pair needed.
            unsigned* cnt_ptr = &g_cnt;
            asm volatile("atom.acq_rel.gpu.global.add.u32 %0, [%1], %2;"
                         : "=r"(old) : "l"(cnt_ptr), "r"(1u) : "memory");
        }
        old = __shfl_sync(0xffffffffu, old, 0);    // warp broadcast

        if (old == LL - 1) {                        // last block: fold 100 values
            volatile float* gp = g_per_label;
            float a = 0.0f;
#pragma unroll
            for (int j = 0; j < 4; j++) {
                const int i2 = lane + j * 32;
                if (i2 < LL) a += gp[i2];
            }
#pragma unroll
            for (int off = 16; off > 0; off >>= 1)
                a += __shfl_down_sync(0xffffffffu, a, off);
            if (lane == 0) {
                out[0] = a / (float)LL;
                g_cnt = 0;                          // reset for next replay
            }
        }
    }
}

extern "C" void kernel_launch(void* const* d_in, const int* in_sizes, int n_in,
                              void* d_out, int out_size) {
    const float* y_pred = (const float*)d_in[0];
    const float* y_true = (const float*)d_in[1];
    const int*   index  = (const int*)d_in[2];
    const float* u_all  = (const float*)d_in[3];
    const float* u_pos  = (const float*)d_in[4];
    float* out = (float*)d_out;

    map_loss_fused_kernel<<<LL, BB>>>(y_pred, y_true, index, u_all, u_pos, out);
}